// round 1
// baseline (speedup 1.0000x reference)
#include <cuda_runtime.h>

#define NN   100000
#define FIN  128
#define HH   64
#define GG   512

// Scratch (device globals — allocation-free per harness rules)
__device__ __align__(16) float g_dinv[NN];
__device__ __align__(16) float g_b0[NN * HH];   // xs (pre-scaled x@W)
__device__ __align__(16) float g_b1[NN * HH];   // acc / h
__device__ __align__(16) float g_pool[GG * HH];
__device__ __align__(16) float g_cnt[GG];

// ---------------------------------------------------------------------------
__global__ void zero_f4_kernel(float* __restrict__ p, int n4) {
    int i = blockIdx.x * blockDim.x + threadIdx.x;
    if (i < n4) ((float4*)p)[i] = make_float4(0.f, 0.f, 0.f, 0.f);
}

__global__ void initdeg_kernel(float* __restrict__ deg, int n) {
    int i = blockIdx.x * blockDim.x + threadIdx.x;
    if (i < n) deg[i] = 1.0f;   // self-loop contributes 1 to every node's degree
}

__global__ void degree_kernel(const int* __restrict__ dst, float* __restrict__ deg, int E) {
    int i = blockIdx.x * blockDim.x + threadIdx.x;
    if (i < E) atomicAdd(&deg[dst[i]], 1.0f);
}

__global__ void rsqrt_kernel(float* __restrict__ deg, int n) {
    int i = blockIdx.x * blockDim.x + threadIdx.x;
    if (i < n) deg[i] = rsqrtf(deg[i]);   // deg >= 1 always (self-loops)
}

// ---------------------------------------------------------------------------
// out[row, :] = dinv[row] * (X[row, :] @ W)     X:[n,K], W:[K,64]
// Block: 256 threads computes 64 rows x 64 cols; K chunked by 32 through smem.
template <int K>
__global__ void gemm_scale_kernel(const float* __restrict__ X,
                                  const float* __restrict__ W,
                                  const float* __restrict__ dinv,
                                  float* __restrict__ out, int n) {
    __shared__ __align__(16) float Ws[K * HH];
    __shared__ __align__(16) float Xs[32][68];   // transposed chunk, padded

    const int row0 = blockIdx.x * 64;
    const int tid  = threadIdx.x;
    const int tx   = tid & 15;    // col group (4 cols each)
    const int ty   = tid >> 4;    // row group (4 rows each)

    for (int i = tid; i < K * HH; i += 256) Ws[i] = W[i];

    float acc[4][4] = {};

    for (int kc = 0; kc < K; kc += 32) {
        __syncthreads();
        // load 64 rows x 32 k, transposed (coalesced global reads)
        #pragma unroll
        for (int j = 0; j < 8; j++) {
            int i = tid + j * 256;        // 0..2047
            int r = i >> 5;
            int k = i & 31;
            int row = row0 + r;
            Xs[k][r] = (row < n) ? X[row * K + kc + k] : 0.0f;
        }
        __syncthreads();

        #pragma unroll
        for (int k = 0; k < 32; k++) {
            float4 b = *(const float4*)&Ws[(kc + k) * HH + tx * 4];
            float4 a = *(const float4*)&Xs[k][ty * 4];
            acc[0][0] += a.x * b.x; acc[0][1] += a.x * b.y; acc[0][2] += a.x * b.z; acc[0][3] += a.x * b.w;
            acc[1][0] += a.y * b.x; acc[1][1] += a.y * b.y; acc[1][2] += a.y * b.z; acc[1][3] += a.y * b.w;
            acc[2][0] += a.z * b.x; acc[2][1] += a.z * b.y; acc[2][2] += a.z * b.z; acc[2][3] += a.z * b.w;
            acc[3][0] += a.w * b.x; acc[3][1] += a.w * b.y; acc[3][2] += a.w * b.z; acc[3][3] += a.w * b.w;
        }
    }

    #pragma unroll
    for (int i = 0; i < 4; i++) {
        int row = row0 + ty * 4 + i;
        if (row < n) {
            float s = dinv[row];
            float4 o = make_float4(acc[i][0] * s, acc[i][1] * s, acc[i][2] * s, acc[i][3] * s);
            *(float4*)&out[row * HH + tx * 4] = o;
        }
    }
}

// ---------------------------------------------------------------------------
// acc[dst] += xs[src]  via vectorized global reductions. 16 threads per edge.
__global__ void scatter_kernel(const int* __restrict__ src, const int* __restrict__ dst,
                               const float* __restrict__ xs, float* __restrict__ acc, int E) {
    int t = blockIdx.x * blockDim.x + threadIdx.x;
    int e = t >> 4;
    if (e >= E) return;
    int c = (t & 15) << 2;
    int s = __ldg(&src[e]);
    int d = __ldg(&dst[e]);
    float4 v = *(const float4*)(xs + s * HH + c);
    float* p = acc + d * HH + c;
    asm volatile("red.global.add.v4.f32 [%0], {%1,%2,%3,%4};"
                 :: "l"(p), "f"(v.x), "f"(v.y), "f"(v.z), "f"(v.w) : "memory");
}

// h[n] = relu(dinv[n] * (acc[n] + xs[n]) + b)   (xs[n] term = self-loop message)
__global__ void finalize_kernel(const float* __restrict__ xs, float* __restrict__ acc,
                                const float* __restrict__ dinv, const float* __restrict__ b,
                                int n) {
    int t = blockIdx.x * blockDim.x + threadIdx.x;
    int node = t >> 4;
    if (node >= n) return;
    int c = (t & 15) << 2;
    float4 a  = *(const float4*)(acc + node * HH + c);
    float4 xv = *(const float4*)(xs  + node * HH + c);
    float4 bb = *(const float4*)(b + c);
    float s = dinv[node];
    float4 o;
    o.x = fmaxf(fmaf(s, a.x + xv.x, bb.x), 0.f);
    o.y = fmaxf(fmaf(s, a.y + xv.y, bb.y), 0.f);
    o.z = fmaxf(fmaf(s, a.z + xv.z, bb.z), 0.f);
    o.w = fmaxf(fmaf(s, a.w + xv.w, bb.w), 0.f);
    *(float4*)(acc + node * HH + c) = o;
}

// ---------------------------------------------------------------------------
__global__ void pool_kernel(const float* __restrict__ h, const int* __restrict__ batch,
                            float* __restrict__ pool, float* __restrict__ cnt, int n) {
    int t = blockIdx.x * blockDim.x + threadIdx.x;
    int node = t >> 4;
    if (node >= n) return;
    int c = (t & 15) << 2;
    int g = __ldg(&batch[node]);
    float4 v = *(const float4*)(h + node * HH + c);
    float* p = pool + g * HH + c;
    asm volatile("red.global.add.v4.f32 [%0], {%1,%2,%3,%4};"
                 :: "l"(p), "f"(v.x), "f"(v.y), "f"(v.z), "f"(v.w) : "memory");
    if ((t & 15) == 0) atomicAdd(&cnt[g], 1.0f);
}

__global__ void head_kernel(const float* __restrict__ pool, const float* __restrict__ cnt,
                            const float* __restrict__ Wl, const float* __restrict__ bl,
                            float* __restrict__ out) {
    int g = blockIdx.x * blockDim.x + threadIdx.x;
    if (g >= GG) return;
    float inv = 1.0f / fmaxf(cnt[g], 1.0f);
    float acc = 0.f;
    #pragma unroll
    for (int k = 0; k < HH; k++) acc += pool[g * HH + k] * __ldg(&Wl[k]);
    float z = acc * inv + __ldg(&bl[0]);
    out[g] = 1.0f / (1.0f + expf(-z));
}

// ---------------------------------------------------------------------------
extern "C" void kernel_launch(void* const* d_in, const int* in_sizes, int n_in,
                              void* d_out, int out_size) {
    const float* x     = (const float*)d_in[0];
    const int*   ei    = (const int*)  d_in[1];
    const int*   batch = (const int*)  d_in[2];
    const float* W1    = (const float*)d_in[3];
    const float* b1    = (const float*)d_in[4];
    const float* W2    = (const float*)d_in[5];
    const float* b2    = (const float*)d_in[6];
    const float* Wl    = (const float*)d_in[7];
    const float* bl    = (const float*)d_in[8];

    const int n = in_sizes[0] / FIN;
    const int E = in_sizes[1] / 2;
    const int* src = ei;
    const int* dst = ei + E;

    float *dinv, *B0, *B1, *pool, *cnt;
    cudaGetSymbolAddress((void**)&dinv, g_dinv);
    cudaGetSymbolAddress((void**)&B0,   g_b0);
    cudaGetSymbolAddress((void**)&B1,   g_b1);
    cudaGetSymbolAddress((void**)&pool, g_pool);
    cudaGetSymbolAddress((void**)&cnt,  g_cnt);

    const int nh4 = n * HH / 4;

    // init: deg=1 (self-loops), acc=0, pool=0, cnt=0
    initdeg_kernel<<<(n + 255) / 256, 256>>>(dinv, n);
    zero_f4_kernel<<<(nh4 + 255) / 256, 256>>>(B1, nh4);
    zero_f4_kernel<<<(GG * HH / 4 + 255) / 256, 256>>>(pool, GG * HH / 4);
    zero_f4_kernel<<<(GG / 4 + 255) / 256, 256>>>(cnt, GG / 4);

    // degrees -> dinv
    degree_kernel<<<(E + 255) / 256, 256>>>(dst, dinv, E);
    rsqrt_kernel<<<(n + 255) / 256, 256>>>(dinv, n);

    // layer 1
    gemm_scale_kernel<FIN><<<(n + 63) / 64, 256>>>(x, W1, dinv, B0, n);
    scatter_kernel<<<(E * 16 + 255) / 256, 256>>>(src, dst, B0, B1, E);
    finalize_kernel<<<(n * 16 + 255) / 256, 256>>>(B0, B1, dinv, b1, n);

    // layer 2
    gemm_scale_kernel<HH><<<(n + 63) / 64, 256>>>(B1, W2, dinv, B0, n);
    zero_f4_kernel<<<(nh4 + 255) / 256, 256>>>(B1, nh4);
    scatter_kernel<<<(E * 16 + 255) / 256, 256>>>(src, dst, B0, B1, E);
    finalize_kernel<<<(n * 16 + 255) / 256, 256>>>(B0, B1, dinv, b2, n);

    // pool + head
    pool_kernel<<<(n * 16 + 255) / 256, 256>>>(B1, batch, pool, cnt, n);
    head_kernel<<<(GG + 255) / 256, 256>>>(pool, cnt, Wl, bl, (float*)d_out);
}

// round 2
// speedup vs baseline: 1.5554x; 1.5554x over previous
#include <cuda_runtime.h>

#define NN   100000
#define FIN  128
#define HH   64
#define GG   512
#define CAP  64

// Scratch (device globals — allocation-free per harness rules)
__device__ __align__(16) float g_dinv[NN];
__device__ __align__(16) float g_b0[NN * HH];      // xs (pre-scaled x@W)
__device__ __align__(16) float g_b1[NN * HH];      // h after layer 1
__device__ __align__(16) float g_pool[GG * HH];
__device__ __align__(16) float g_cnt[GG];
__device__            int   g_deg[NN];             // in-degree counters / cursors
__device__ __align__(16) int g_bucket[NN * CAP];   // incoming src lists per node

// ---------------------------------------------------------------------------
__global__ void zero_f4_kernel(float* __restrict__ p, int n4) {
    int i = blockIdx.x * blockDim.x + threadIdx.x;
    if (i < n4) ((float4*)p)[i] = make_float4(0.f, 0.f, 0.f, 0.f);
}

__global__ void zero_i_kernel(int* __restrict__ p, int n) {
    int i = blockIdx.x * blockDim.x + threadIdx.x;
    if (i < n) p[i] = 0;
}

// bucket fill: pos = cursor[dst]++ ; bucket[dst*CAP+pos] = src
__global__ void fill_kernel(const int* __restrict__ src, const int* __restrict__ dst,
                            int* __restrict__ cur, int* __restrict__ bucket, int E) {
    int i = blockIdx.x * blockDim.x + threadIdx.x;
    if (i >= E) return;
    int d = __ldg(&dst[i]);
    int pos = atomicAdd(&cur[d], 1);
    if (pos < CAP) bucket[d * CAP + pos] = __ldg(&src[i]);
}

// dinv = rsqrt(deg + 1)  (self-loop adds 1)
__global__ void dinv_kernel(const int* __restrict__ deg, float* __restrict__ dinv, int n) {
    int i = blockIdx.x * blockDim.x + threadIdx.x;
    if (i < n) dinv[i] = rsqrtf((float)deg[i] + 1.0f);
}

// ---------------------------------------------------------------------------
// out[row, :] = dinv[row] * (X[row, :] @ W)     X:[n,K], W:[K,64]
template <int K>
__global__ void gemm_scale_kernel(const float* __restrict__ X,
                                  const float* __restrict__ W,
                                  const float* __restrict__ dinv,
                                  float* __restrict__ out, int n) {
    __shared__ __align__(16) float Ws[K * HH];
    __shared__ __align__(16) float Xs[32][68];

    const int row0 = blockIdx.x * 64;
    const int tid  = threadIdx.x;
    const int tx   = tid & 15;    // col group (4 cols each)
    const int ty   = tid >> 4;    // row group (4 rows each)

    for (int i = tid; i < K * HH; i += 256) Ws[i] = W[i];

    float acc[4][4] = {};

    for (int kc = 0; kc < K; kc += 32) {
        __syncthreads();
        #pragma unroll
        for (int j = 0; j < 8; j++) {
            int i = tid + j * 256;
            int r = i >> 5;
            int k = i & 31;
            int row = row0 + r;
            Xs[k][r] = (row < n) ? X[row * K + kc + k] : 0.0f;
        }
        __syncthreads();

        #pragma unroll
        for (int k = 0; k < 32; k++) {
            float4 b = *(const float4*)&Ws[(kc + k) * HH + tx * 4];
            float4 a = *(const float4*)&Xs[k][ty * 4];
            acc[0][0] += a.x * b.x; acc[0][1] += a.x * b.y; acc[0][2] += a.x * b.z; acc[0][3] += a.x * b.w;
            acc[1][0] += a.y * b.x; acc[1][1] += a.y * b.y; acc[1][2] += a.y * b.z; acc[1][3] += a.y * b.w;
            acc[2][0] += a.z * b.x; acc[2][1] += a.z * b.y; acc[2][2] += a.z * b.z; acc[2][3] += a.z * b.w;
            acc[3][0] += a.w * b.x; acc[3][1] += a.w * b.y; acc[3][2] += a.w * b.z; acc[3][3] += a.w * b.w;
        }
    }

    #pragma unroll
    for (int i = 0; i < 4; i++) {
        int row = row0 + ty * 4 + i;
        if (row < n) {
            float s = dinv[row];
            float4 o = make_float4(acc[i][0] * s, acc[i][1] * s, acc[i][2] * s, acc[i][3] * s);
            *(float4*)&out[row * HH + tx * 4] = o;
        }
    }
}

// ---------------------------------------------------------------------------
// Gather layer: out[n] = relu(dinv[n] * (xs[n] + sum_{s in bucket[n]} xs[s]) + b)
// 16 threads per node, each owns a float4 (4 columns).
// POOL=true: instead of storing, reduce into pool[batch[n]] and count nodes.
template <bool POOL>
__global__ void gather_kernel(const int* __restrict__ deg, const int* __restrict__ bucket,
                              const float* __restrict__ xs, const float* __restrict__ dinv,
                              const float* __restrict__ b,
                              float* __restrict__ out,
                              const int* __restrict__ batch,
                              float* __restrict__ pool, float* __restrict__ cntg,
                              int n) {
    int t = blockIdx.x * blockDim.x + threadIdx.x;
    int node = t >> 4;
    if (node >= n) return;
    int c = (t & 15) << 2;

    int dcount = __ldg(&deg[node]);
    if (dcount > CAP) dcount = CAP;
    const int* lst = bucket + node * CAP;

    // self-loop message
    float4 acc = *(const float4*)(xs + node * HH + c);

    int e = 0;
    for (; e + 4 <= dcount; e += 4) {
        int s0 = __ldg(&lst[e + 0]);
        int s1 = __ldg(&lst[e + 1]);
        int s2 = __ldg(&lst[e + 2]);
        int s3 = __ldg(&lst[e + 3]);
        float4 v0 = *(const float4*)(xs + s0 * HH + c);
        float4 v1 = *(const float4*)(xs + s1 * HH + c);
        float4 v2 = *(const float4*)(xs + s2 * HH + c);
        float4 v3 = *(const float4*)(xs + s3 * HH + c);
        acc.x += v0.x + v1.x + v2.x + v3.x;
        acc.y += v0.y + v1.y + v2.y + v3.y;
        acc.z += v0.z + v1.z + v2.z + v3.z;
        acc.w += v0.w + v1.w + v2.w + v3.w;
    }
    for (; e < dcount; e++) {
        int s = __ldg(&lst[e]);
        float4 v = *(const float4*)(xs + s * HH + c);
        acc.x += v.x; acc.y += v.y; acc.z += v.z; acc.w += v.w;
    }

    float sc = __ldg(&dinv[node]);
    float4 bb = *(const float4*)(b + c);
    float4 o;
    o.x = fmaxf(fmaf(sc, acc.x, bb.x), 0.f);
    o.y = fmaxf(fmaf(sc, acc.y, bb.y), 0.f);
    o.z = fmaxf(fmaf(sc, acc.z, bb.z), 0.f);
    o.w = fmaxf(fmaf(sc, acc.w, bb.w), 0.f);

    if (!POOL) {
        *(float4*)(out + node * HH + c) = o;
    } else {
        int g = __ldg(&batch[node]);
        float* p = pool + g * HH + c;
        asm volatile("red.global.add.v4.f32 [%0], {%1,%2,%3,%4};"
                     :: "l"(p), "f"(o.x), "f"(o.y), "f"(o.z), "f"(o.w) : "memory");
        if ((t & 15) == 0) atomicAdd(&cntg[g], 1.0f);
    }
}

// ---------------------------------------------------------------------------
__global__ void head_kernel(const float* __restrict__ pool, const float* __restrict__ cnt,
                            const float* __restrict__ Wl, const float* __restrict__ bl,
                            float* __restrict__ out) {
    int g = blockIdx.x * blockDim.x + threadIdx.x;
    if (g >= GG) return;
    float inv = 1.0f / fmaxf(cnt[g], 1.0f);
    float acc = 0.f;
    #pragma unroll
    for (int k = 0; k < HH; k++) acc += pool[g * HH + k] * __ldg(&Wl[k]);
    float z = acc * inv + __ldg(&bl[0]);
    out[g] = 1.0f / (1.0f + expf(-z));
}

// ---------------------------------------------------------------------------
extern "C" void kernel_launch(void* const* d_in, const int* in_sizes, int n_in,
                              void* d_out, int out_size) {
    const float* x     = (const float*)d_in[0];
    const int*   ei    = (const int*)  d_in[1];
    const int*   batch = (const int*)  d_in[2];
    const float* W1    = (const float*)d_in[3];
    const float* b1    = (const float*)d_in[4];
    const float* W2    = (const float*)d_in[5];
    const float* b2    = (const float*)d_in[6];
    const float* Wl    = (const float*)d_in[7];
    const float* bl    = (const float*)d_in[8];

    const int n = in_sizes[0] / FIN;
    const int E = in_sizes[1] / 2;
    const int* src = ei;
    const int* dst = ei + E;

    float *dinv, *B0, *B1, *pool, *cnt;
    int *deg, *bucket;
    cudaGetSymbolAddress((void**)&dinv,   g_dinv);
    cudaGetSymbolAddress((void**)&B0,     g_b0);
    cudaGetSymbolAddress((void**)&B1,     g_b1);
    cudaGetSymbolAddress((void**)&pool,   g_pool);
    cudaGetSymbolAddress((void**)&cnt,    g_cnt);
    cudaGetSymbolAddress((void**)&deg,    g_deg);
    cudaGetSymbolAddress((void**)&bucket, g_bucket);

    // init
    zero_i_kernel<<<(n + 255) / 256, 256>>>(deg, n);
    zero_f4_kernel<<<(GG * HH / 4 + 255) / 256, 256>>>(pool, GG * HH / 4);
    zero_f4_kernel<<<(GG / 4 + 255) / 256, 256>>>(cnt, GG / 4);

    // adjacency build (once, reused by both layers)
    fill_kernel<<<(E + 255) / 256, 256>>>(src, dst, deg, bucket, E);
    dinv_kernel<<<(n + 255) / 256, 256>>>(deg, dinv, n);

    // layer 1: xs = dinv*(x@W1) ; h1 = relu(dinv*(gather + self) + b1)
    gemm_scale_kernel<FIN><<<(n + 63) / 64, 256>>>(x, W1, dinv, B0, n);
    gather_kernel<false><<<(n * 16 + 255) / 256, 256>>>(
        deg, bucket, B0, dinv, b1, B1, nullptr, nullptr, nullptr, n);

    // layer 2: xs = dinv*(h1@W2) ; h2 = relu(...) fused with mean-pool reduction
    gemm_scale_kernel<HH><<<(n + 63) / 64, 256>>>(B1, W2, dinv, B0, n);
    gather_kernel<true><<<(n * 16 + 255) / 256, 256>>>(
        deg, bucket, B0, dinv, b2, nullptr, batch, pool, cnt, n);

    // head
    head_kernel<<<(GG + 255) / 256, 256>>>(pool, cnt, Wl, bl, (float*)d_out);
}

// round 3
// speedup vs baseline: 1.7186x; 1.1050x over previous
#include <cuda_runtime.h>
#include <cstdint>

#define NN   100000
#define FIN  128
#define HH   64
#define GG   512
#define CAP  64

// Scratch (device globals — allocation-free per harness rules)
__device__ __align__(16) float g_dinv[NN];
__device__ __align__(16) float g_b0[NN * HH];      // xs (pre-scaled x@W)
__device__ __align__(16) float g_b1[NN * HH];      // h after layer 1
__device__ __align__(16) float g_pool[GG * HH];
__device__ __align__(16) float g_cnt[GG];
__device__            int   g_deg[NN];             // in-degree counters / cursors
__device__ __align__(16) int g_bucket[NN * CAP];   // incoming src lists per node

// ---------------------------------------------------------------------------
__global__ void zero_f4_kernel(float* __restrict__ p, int n4) {
    int i = blockIdx.x * blockDim.x + threadIdx.x;
    if (i < n4) ((float4*)p)[i] = make_float4(0.f, 0.f, 0.f, 0.f);
}

__global__ void zero_i_kernel(int* __restrict__ p, int n) {
    int i = blockIdx.x * blockDim.x + threadIdx.x;
    if (i < n) p[i] = 0;
}

// bucket fill, 4 edges per thread for atomic-latency MLP
__global__ void fill_kernel(const int* __restrict__ src, const int* __restrict__ dst,
                            int* __restrict__ cur, int* __restrict__ bucket, int E) {
    int base = (blockIdx.x * blockDim.x + threadIdx.x) * 4;
    #pragma unroll
    for (int j = 0; j < 4; j++) {
        int i = base + j;
        if (i < E) {
            int d = __ldg(&dst[i]);
            int s = __ldg(&src[i]);
            int pos = atomicAdd(&cur[d], 1);
            if (pos < CAP) bucket[d * CAP + pos] = s;
        }
    }
}

// dinv = rsqrt(deg + 1)  (self-loop adds 1)
__global__ void dinv_kernel(const int* __restrict__ deg, float* __restrict__ dinv, int n) {
    int i = blockIdx.x * blockDim.x + threadIdx.x;
    if (i < n) dinv[i] = rsqrtf((float)deg[i] + 1.0f);
}

// ---------------------------------------------------------------------------
// Tensor-core GEMM: out[row,:] = dinv[row] * (X[row,:] @ W),  W:[K,64]
// mma.sync.m16n8k8 tf32. Block: 128 threads (4 warps), tile M=128, N=64.
#define WS_STRIDE 72   // ≡8 (mod 32): B-frag reads conflict-free
#define AS_STRIDE 20   // ≡4 (mod 32): A-frag reads conflict-free (chunk=16)

__device__ __forceinline__ uint32_t f2tf32(float f) {
    uint32_t r;
    asm("cvt.rna.tf32.f32 %0, %1;" : "=r"(r) : "f"(f));
    return r;
}

template <int K>
__global__ __launch_bounds__(128) void gemm_mma_kernel(
        const float* __restrict__ X, const float* __restrict__ W,
        const float* __restrict__ dinv, float* __restrict__ out, int n) {
    __shared__ uint32_t Ws[K * WS_STRIDE];
    __shared__ uint32_t As[128 * AS_STRIDE];

    const int tid  = threadIdx.x;
    const int row0 = blockIdx.x * 128;
    const int warp = tid >> 5;
    const int lane = tid & 31;
    const int r    = lane >> 2;     // 0..7
    const int cq   = lane & 3;      // 0..3
    const int mrow = warp * 32;

    // stage W (tf32-rounded), coalesced
    for (int i = tid; i < K * 64; i += 128) {
        int k = i >> 6, nn = i & 63;
        Ws[k * WS_STRIDE + nn] = f2tf32(W[i]);
    }

    float acc[2][8][4];
    #pragma unroll
    for (int mt = 0; mt < 2; mt++)
        #pragma unroll
        for (int nb = 0; nb < 8; nb++)
            #pragma unroll
            for (int c = 0; c < 4; c++) acc[mt][nb][c] = 0.f;

    for (int kc = 0; kc < K; kc += 16) {
        __syncthreads();
        // stage A chunk [128 rows x 16 k]
        #pragma unroll
        for (int j = 0; j < 16; j++) {
            int i   = tid + j * 128;          // 0..2047
            int rr  = i >> 4;
            int c   = i & 15;
            int row = row0 + rr;
            float v = (row < n) ? X[(long)row * K + kc + c] : 0.0f;
            As[rr * AS_STRIDE + c] = f2tf32(v);
        }
        __syncthreads();

        #pragma unroll
        for (int ks = 0; ks < 2; ks++) {
            int kl = ks * 8;                 // local k within chunk
            uint32_t a[2][4];
            #pragma unroll
            for (int mt = 0; mt < 2; mt++) {
                int rr = mrow + mt * 16;
                a[mt][0] = As[(rr + r)     * AS_STRIDE + kl + cq];
                a[mt][1] = As[(rr + r + 8) * AS_STRIDE + kl + cq];
                a[mt][2] = As[(rr + r)     * AS_STRIDE + kl + cq + 4];
                a[mt][3] = As[(rr + r + 8) * AS_STRIDE + kl + cq + 4];
            }
            #pragma unroll
            for (int nb = 0; nb < 8; nb++) {
                uint32_t b0 = Ws[(kc + kl + cq)     * WS_STRIDE + nb * 8 + r];
                uint32_t b1 = Ws[(kc + kl + cq + 4) * WS_STRIDE + nb * 8 + r];
                #pragma unroll
                for (int mt = 0; mt < 2; mt++) {
                    asm volatile(
                        "mma.sync.aligned.m16n8k8.row.col.f32.tf32.tf32.f32 "
                        "{%0,%1,%2,%3}, {%4,%5,%6,%7}, {%8,%9}, {%0,%1,%2,%3};"
                        : "+f"(acc[mt][nb][0]), "+f"(acc[mt][nb][1]),
                          "+f"(acc[mt][nb][2]), "+f"(acc[mt][nb][3])
                        : "r"(a[mt][0]), "r"(a[mt][1]), "r"(a[mt][2]), "r"(a[mt][3]),
                          "r"(b0), "r"(b1));
                }
            }
        }
    }

    // epilogue: scale by dinv, store float2 pairs
    #pragma unroll
    for (int mt = 0; mt < 2; mt++) {
        int row_a = row0 + mrow + mt * 16 + r;
        int row_b = row_a + 8;
        float sa = (row_a < n) ? dinv[row_a] : 0.f;
        float sb = (row_b < n) ? dinv[row_b] : 0.f;
        #pragma unroll
        for (int nb = 0; nb < 8; nb++) {
            int col = nb * 8 + cq * 2;
            if (row_a < n) {
                float2 v = make_float2(acc[mt][nb][0] * sa, acc[mt][nb][1] * sa);
                *(float2*)&out[(long)row_a * HH + col] = v;
            }
            if (row_b < n) {
                float2 v = make_float2(acc[mt][nb][2] * sb, acc[mt][nb][3] * sb);
                *(float2*)&out[(long)row_b * HH + col] = v;
            }
        }
    }
}

// ---------------------------------------------------------------------------
// Gather layer: out[n] = relu(dinv[n] * (xs[n] + sum_{s in bucket[n]} xs[s]) + b)
// 16 threads per node, each owns a float4 (4 columns).
// POOL=true: instead of storing, reduce into pool[batch[n]] and count nodes.
template <bool POOL>
__global__ void gather_kernel(const int* __restrict__ deg, const int* __restrict__ bucket,
                              const float* __restrict__ xs, const float* __restrict__ dinv,
                              const float* __restrict__ b,
                              float* __restrict__ out,
                              const int* __restrict__ batch,
                              float* __restrict__ pool, float* __restrict__ cntg,
                              int n) {
    int t = blockIdx.x * blockDim.x + threadIdx.x;
    int node = t >> 4;
    if (node >= n) return;
    int c = (t & 15) << 2;

    int dcount = __ldg(&deg[node]);
    if (dcount > CAP) dcount = CAP;
    const int* lst = bucket + node * CAP;

    float4 acc = *(const float4*)(xs + node * HH + c);   // self-loop message

    int e = 0;
    for (; e + 4 <= dcount; e += 4) {
        int s0 = __ldg(&lst[e + 0]);
        int s1 = __ldg(&lst[e + 1]);
        int s2 = __ldg(&lst[e + 2]);
        int s3 = __ldg(&lst[e + 3]);
        float4 v0 = *(const float4*)(xs + s0 * HH + c);
        float4 v1 = *(const float4*)(xs + s1 * HH + c);
        float4 v2 = *(const float4*)(xs + s2 * HH + c);
        float4 v3 = *(const float4*)(xs + s3 * HH + c);
        acc.x += v0.x + v1.x + v2.x + v3.x;
        acc.y += v0.y + v1.y + v2.y + v3.y;
        acc.z += v0.z + v1.z + v2.z + v3.z;
        acc.w += v0.w + v1.w + v2.w + v3.w;
    }
    for (; e < dcount; e++) {
        int s = __ldg(&lst[e]);
        float4 v = *(const float4*)(xs + s * HH + c);
        acc.x += v.x; acc.y += v.y; acc.z += v.z; acc.w += v.w;
    }

    float sc = __ldg(&dinv[node]);
    float4 bb = *(const float4*)(b + c);
    float4 o;
    o.x = fmaxf(fmaf(sc, acc.x, bb.x), 0.f);
    o.y = fmaxf(fmaf(sc, acc.y, bb.y), 0.f);
    o.z = fmaxf(fmaf(sc, acc.z, bb.z), 0.f);
    o.w = fmaxf(fmaf(sc, acc.w, bb.w), 0.f);

    if (!POOL) {
        *(float4*)(out + node * HH + c) = o;
    } else {
        int g = __ldg(&batch[node]);
        float* p = pool + g * HH + c;
        asm volatile("red.global.add.v4.f32 [%0], {%1,%2,%3,%4};"
                     :: "l"(p), "f"(o.x), "f"(o.y), "f"(o.z), "f"(o.w) : "memory");
        if ((t & 15) == 0) atomicAdd(&cntg[g], 1.0f);
    }
}

// ---------------------------------------------------------------------------
__global__ void head_kernel(const float* __restrict__ pool, const float* __restrict__ cnt,
                            const float* __restrict__ Wl, const float* __restrict__ bl,
                            float* __restrict__ out) {
    int g = blockIdx.x * blockDim.x + threadIdx.x;
    if (g >= GG) return;
    float inv = 1.0f / fmaxf(cnt[g], 1.0f);
    float acc = 0.f;
    #pragma unroll
    for (int k = 0; k < HH; k++) acc += pool[g * HH + k] * __ldg(&Wl[k]);
    float z = acc * inv + __ldg(&bl[0]);
    out[g] = 1.0f / (1.0f + expf(-z));
}

// ---------------------------------------------------------------------------
extern "C" void kernel_launch(void* const* d_in, const int* in_sizes, int n_in,
                              void* d_out, int out_size) {
    const float* x     = (const float*)d_in[0];
    const int*   ei    = (const int*)  d_in[1];
    const int*   batch = (const int*)  d_in[2];
    const float* W1    = (const float*)d_in[3];
    const float* b1    = (const float*)d_in[4];
    const float* W2    = (const float*)d_in[5];
    const float* b2    = (const float*)d_in[6];
    const float* Wl    = (const float*)d_in[7];
    const float* bl    = (const float*)d_in[8];

    const int n = in_sizes[0] / FIN;
    const int E = in_sizes[1] / 2;
    const int* src = ei;
    const int* dst = ei + E;

    float *dinv, *B0, *B1, *pool, *cnt;
    int *deg, *bucket;
    cudaGetSymbolAddress((void**)&dinv,   g_dinv);
    cudaGetSymbolAddress((void**)&B0,     g_b0);
    cudaGetSymbolAddress((void**)&B1,     g_b1);
    cudaGetSymbolAddress((void**)&pool,   g_pool);
    cudaGetSymbolAddress((void**)&cnt,    g_cnt);
    cudaGetSymbolAddress((void**)&deg,    g_deg);
    cudaGetSymbolAddress((void**)&bucket, g_bucket);

    // init
    zero_i_kernel<<<(n + 255) / 256, 256>>>(deg, n);
    zero_f4_kernel<<<(GG * HH / 4 + 255) / 256, 256>>>(pool, GG * HH / 4);
    zero_f4_kernel<<<(GG / 4 + 255) / 256, 256>>>(cnt, GG / 4);

    // adjacency build (once, reused by both layers)
    fill_kernel<<<(E / 4 + 255) / 256, 256>>>(src, dst, deg, bucket, E);
    dinv_kernel<<<(n + 255) / 256, 256>>>(deg, dinv, n);

    // layer 1: xs = dinv*(x@W1) ; h1 = relu(dinv*(gather + self) + b1)
    gemm_mma_kernel<FIN><<<(n + 127) / 128, 128>>>(x, W1, dinv, B0, n);
    gather_kernel<false><<<(n * 16 + 255) / 256, 256>>>(
        deg, bucket, B0, dinv, b1, B1, nullptr, nullptr, nullptr, n);

    // layer 2: xs = dinv*(h1@W2) ; fused relu + mean-pool reduction
    gemm_mma_kernel<HH><<<(n + 127) / 128, 128>>>(B1, W2, dinv, B0, n);
    gather_kernel<true><<<(n * 16 + 255) / 256, 256>>>(
        deg, bucket, B0, dinv, b2, nullptr, batch, pool, cnt, n);

    // head
    head_kernel<<<(GG + 255) / 256, 256>>>(pool, cnt, Wl, bl, (float*)d_out);
}

// round 4
// speedup vs baseline: 1.9919x; 1.1590x over previous
#include <cuda_runtime.h>
#include <cuda_bf16.h>
#include <cstdint>

#define NN   100000
#define FIN  128
#define HH   64
#define GG   512
#define CAP  64

// Scratch (device globals — allocation-free per harness rules)
__device__ __align__(16) float g_dinv[NN];
__device__ __align__(16) __nv_bfloat16 g_xs[NN * HH];  // scaled x@W (bf16)
__device__ __align__(16) __nv_bfloat16 g_h1[NN * HH];  // h after layer 1 (bf16)
__device__ __align__(16) float g_pool[GG * HH];
__device__ __align__(16) float g_cnt[GG];
__device__            int   g_deg[NN];
__device__ __align__(16) int g_bucket[NN * CAP];

// ---------------------------------------------------------------------------
__global__ void zero_f4_kernel(float* __restrict__ p, int n4) {
    int i = blockIdx.x * blockDim.x + threadIdx.x;
    if (i < n4) ((float4*)p)[i] = make_float4(0.f, 0.f, 0.f, 0.f);
}

__global__ void zero_i_kernel(int* __restrict__ p, int n) {
    int i = blockIdx.x * blockDim.x + threadIdx.x;
    if (i < n) p[i] = 0;
}

// bucket fill, 4 edges per thread
__global__ void fill_kernel(const int* __restrict__ src, const int* __restrict__ dst,
                            int* __restrict__ cur, int* __restrict__ bucket, int E) {
    int base = (blockIdx.x * blockDim.x + threadIdx.x) * 4;
    #pragma unroll
    for (int j = 0; j < 4; j++) {
        int i = base + j;
        if (i < E) {
            int d = __ldg(&dst[i]);
            int s = __ldg(&src[i]);
            int pos = atomicAdd(&cur[d], 1);
            if (pos < CAP) bucket[d * CAP + pos] = s;
        }
    }
}

__global__ void dinv_kernel(const int* __restrict__ deg, float* __restrict__ dinv, int n) {
    int i = blockIdx.x * blockDim.x + threadIdx.x;
    if (i < n) dinv[i] = rsqrtf((float)deg[i] + 1.0f);
}

// ---------------------------------------------------------------------------
// Tensor-core GEMM: out[row,:] = bf16( dinv[row] * (X[row,:] @ W) ),  W:[K,64] fp32
// mma.sync.m16n8k8 tf32. Block: 128 threads (4 warps), tile M=128, N=64.
// BF16IN: X is bf16 (exact tf32 operand via <<16); else fp32 (rna-rounded).
#define WS_STRIDE 72
#define AS_STRIDE 20

__device__ __forceinline__ uint32_t f2tf32(float f) {
    uint32_t r;
    asm("cvt.rna.tf32.f32 %0, %1;" : "=r"(r) : "f"(f));
    return r;
}

template <int K, bool BF16IN>
__global__ __launch_bounds__(128) void gemm_mma_kernel(
        const void* __restrict__ Xv, const float* __restrict__ W,
        const float* __restrict__ dinv, __nv_bfloat16* __restrict__ out, int n) {
    __shared__ uint32_t Ws[K * WS_STRIDE];
    __shared__ uint32_t As[128 * AS_STRIDE];

    const int tid  = threadIdx.x;
    const int row0 = blockIdx.x * 128;
    const int warp = tid >> 5;
    const int lane = tid & 31;
    const int r    = lane >> 2;
    const int cq   = lane & 3;
    const int mrow = warp * 32;

    for (int i = tid; i < K * 64; i += 128) {
        int k = i >> 6, nn = i & 63;
        Ws[k * WS_STRIDE + nn] = f2tf32(W[i]);
    }

    float acc[2][8][4];
    #pragma unroll
    for (int mt = 0; mt < 2; mt++)
        #pragma unroll
        for (int nb = 0; nb < 8; nb++)
            #pragma unroll
            for (int c = 0; c < 4; c++) acc[mt][nb][c] = 0.f;

    for (int kc = 0; kc < K; kc += 16) {
        __syncthreads();
        #pragma unroll
        for (int j = 0; j < 16; j++) {
            int i   = tid + j * 128;
            int rr  = i >> 4;
            int c   = i & 15;
            int row = row0 + rr;
            uint32_t v;
            if (BF16IN) {
                const __nv_bfloat16* X = (const __nv_bfloat16*)Xv;
                uint16_t h = (row < n) ? *(const uint16_t*)&X[(long)row * K + kc + c] : 0;
                v = ((uint32_t)h) << 16;   // exact tf32
            } else {
                const float* X = (const float*)Xv;
                float f = (row < n) ? X[(long)row * K + kc + c] : 0.0f;
                v = f2tf32(f);
            }
            As[rr * AS_STRIDE + c] = v;
        }
        __syncthreads();

        #pragma unroll
        for (int ks = 0; ks < 2; ks++) {
            int kl = ks * 8;
            uint32_t a[2][4];
            #pragma unroll
            for (int mt = 0; mt < 2; mt++) {
                int rr = mrow + mt * 16;
                a[mt][0] = As[(rr + r)     * AS_STRIDE + kl + cq];
                a[mt][1] = As[(rr + r + 8) * AS_STRIDE + kl + cq];
                a[mt][2] = As[(rr + r)     * AS_STRIDE + kl + cq + 4];
                a[mt][3] = As[(rr + r + 8) * AS_STRIDE + kl + cq + 4];
            }
            #pragma unroll
            for (int nb = 0; nb < 8; nb++) {
                uint32_t b0 = Ws[(kc + kl + cq)     * WS_STRIDE + nb * 8 + r];
                uint32_t b1 = Ws[(kc + kl + cq + 4) * WS_STRIDE + nb * 8 + r];
                #pragma unroll
                for (int mt = 0; mt < 2; mt++) {
                    asm volatile(
                        "mma.sync.aligned.m16n8k8.row.col.f32.tf32.tf32.f32 "
                        "{%0,%1,%2,%3}, {%4,%5,%6,%7}, {%8,%9}, {%0,%1,%2,%3};"
                        : "+f"(acc[mt][nb][0]), "+f"(acc[mt][nb][1]),
                          "+f"(acc[mt][nb][2]), "+f"(acc[mt][nb][3])
                        : "r"(a[mt][0]), "r"(a[mt][1]), "r"(a[mt][2]), "r"(a[mt][3]),
                          "r"(b0), "r"(b1));
                }
            }
        }
    }

    // epilogue: scale by dinv, store bf16x2 pairs
    #pragma unroll
    for (int mt = 0; mt < 2; mt++) {
        int row_a = row0 + mrow + mt * 16 + r;
        int row_b = row_a + 8;
        float sa = (row_a < n) ? dinv[row_a] : 0.f;
        float sb = (row_b < n) ? dinv[row_b] : 0.f;
        #pragma unroll
        for (int nb = 0; nb < 8; nb++) {
            int col = nb * 8 + cq * 2;
            if (row_a < n) {
                __nv_bfloat162 v = __float22bfloat162_rn(
                    make_float2(acc[mt][nb][0] * sa, acc[mt][nb][1] * sa));
                *(__nv_bfloat162*)&out[(long)row_a * HH + col] = v;
            }
            if (row_b < n) {
                __nv_bfloat162 v = __float22bfloat162_rn(
                    make_float2(acc[mt][nb][2] * sb, acc[mt][nb][3] * sb));
                *(__nv_bfloat162*)&out[(long)row_b * HH + col] = v;
            }
        }
    }
}

// ---------------------------------------------------------------------------
// Gather: h[n] = relu(dinv[n] * (xs[n] + sum_{s in bucket} xs[s]) + b)
// bf16 rows (128 B). 8 threads per node, each lane owns one uint4 (8 bf16).
__device__ __forceinline__ void acc_u4(float* a, uint4 v) {
    float2 f;
    f = __bfloat1622float2(*(__nv_bfloat162*)&v.x); a[0] += f.x; a[1] += f.y;
    f = __bfloat1622float2(*(__nv_bfloat162*)&v.y); a[2] += f.x; a[3] += f.y;
    f = __bfloat1622float2(*(__nv_bfloat162*)&v.z); a[4] += f.x; a[5] += f.y;
    f = __bfloat1622float2(*(__nv_bfloat162*)&v.w); a[6] += f.x; a[7] += f.y;
}

template <bool POOL>
__global__ void gather_kernel(const int* __restrict__ deg, const int* __restrict__ bucket,
                              const __nv_bfloat16* __restrict__ xs,
                              const float* __restrict__ dinv,
                              const float* __restrict__ b,
                              __nv_bfloat16* __restrict__ out,
                              const int* __restrict__ batch,
                              float* __restrict__ pool, float* __restrict__ cntg,
                              int n) {
    int t = blockIdx.x * blockDim.x + threadIdx.x;
    int node = t >> 3;
    if (node >= n) return;
    int lane8 = t & 7;
    int c = lane8 << 3;                    // column base (8 cols)
    const uint4* xrow = (const uint4*)(xs) + node * 8 + lane8;  // HH bf16 = 8 uint4

    int dcount = __ldg(&deg[node]);
    if (dcount > CAP) dcount = CAP;
    const int* lst = bucket + node * CAP;

    float acc[8] = {};
    acc_u4(acc, __ldg((const uint4*)xs + (long)node * 8 + lane8));  // self-loop

    int e = 0;
    for (; e + 4 <= dcount; e += 4) {
        int s0 = __ldg(&lst[e + 0]);
        int s1 = __ldg(&lst[e + 1]);
        int s2 = __ldg(&lst[e + 2]);
        int s3 = __ldg(&lst[e + 3]);
        uint4 v0 = __ldg((const uint4*)xs + (long)s0 * 8 + lane8);
        uint4 v1 = __ldg((const uint4*)xs + (long)s1 * 8 + lane8);
        uint4 v2 = __ldg((const uint4*)xs + (long)s2 * 8 + lane8);
        uint4 v3 = __ldg((const uint4*)xs + (long)s3 * 8 + lane8);
        acc_u4(acc, v0); acc_u4(acc, v1); acc_u4(acc, v2); acc_u4(acc, v3);
    }
    for (; e < dcount; e++) {
        int s = __ldg(&lst[e]);
        acc_u4(acc, __ldg((const uint4*)xs + (long)s * 8 + lane8));
    }
    (void)xrow;

    float sc = __ldg(&dinv[node]);
    float o[8];
    #pragma unroll
    for (int i = 0; i < 8; i++)
        o[i] = fmaxf(fmaf(sc, acc[i], __ldg(&b[c + i])), 0.f);

    if (!POOL) {
        uint4 pk;
        __nv_bfloat162 h0 = __float22bfloat162_rn(make_float2(o[0], o[1]));
        __nv_bfloat162 h1 = __float22bfloat162_rn(make_float2(o[2], o[3]));
        __nv_bfloat162 h2 = __float22bfloat162_rn(make_float2(o[4], o[5]));
        __nv_bfloat162 h3 = __float22bfloat162_rn(make_float2(o[6], o[7]));
        pk.x = *(uint32_t*)&h0; pk.y = *(uint32_t*)&h1;
        pk.z = *(uint32_t*)&h2; pk.w = *(uint32_t*)&h3;
        *((uint4*)out + (long)node * 8 + lane8) = pk;
    } else {
        int g = __ldg(&batch[node]);
        float* p = pool + g * HH + c;
        asm volatile("red.global.add.v4.f32 [%0], {%1,%2,%3,%4};"
                     :: "l"(p), "f"(o[0]), "f"(o[1]), "f"(o[2]), "f"(o[3]) : "memory");
        asm volatile("red.global.add.v4.f32 [%0], {%1,%2,%3,%4};"
                     :: "l"(p + 4), "f"(o[4]), "f"(o[5]), "f"(o[6]), "f"(o[7]) : "memory");
        if (lane8 == 0) atomicAdd(&cntg[g], 1.0f);
    }
}

// ---------------------------------------------------------------------------
__global__ void head_kernel(const float* __restrict__ pool, const float* __restrict__ cnt,
                            const float* __restrict__ Wl, const float* __restrict__ bl,
                            float* __restrict__ out) {
    int g = blockIdx.x * blockDim.x + threadIdx.x;
    if (g >= GG) return;
    float inv = 1.0f / fmaxf(cnt[g], 1.0f);
    float acc = 0.f;
    #pragma unroll
    for (int k = 0; k < HH; k++) acc += pool[g * HH + k] * __ldg(&Wl[k]);
    float z = acc * inv + __ldg(&bl[0]);
    out[g] = 1.0f / (1.0f + expf(-z));
}

// ---------------------------------------------------------------------------
extern "C" void kernel_launch(void* const* d_in, const int* in_sizes, int n_in,
                              void* d_out, int out_size) {
    const float* x     = (const float*)d_in[0];
    const int*   ei    = (const int*)  d_in[1];
    const int*   batch = (const int*)  d_in[2];
    const float* W1    = (const float*)d_in[3];
    const float* b1    = (const float*)d_in[4];
    const float* W2    = (const float*)d_in[5];
    const float* b2    = (const float*)d_in[6];
    const float* Wl    = (const float*)d_in[7];
    const float* bl    = (const float*)d_in[8];

    const int n = in_sizes[0] / FIN;
    const int E = in_sizes[1] / 2;
    const int* src = ei;
    const int* dst = ei + E;

    float *dinv, *pool, *cnt;
    __nv_bfloat16 *XS, *H1;
    int *deg, *bucket;
    cudaGetSymbolAddress((void**)&dinv,   g_dinv);
    cudaGetSymbolAddress((void**)&XS,     g_xs);
    cudaGetSymbolAddress((void**)&H1,     g_h1);
    cudaGetSymbolAddress((void**)&pool,   g_pool);
    cudaGetSymbolAddress((void**)&cnt,    g_cnt);
    cudaGetSymbolAddress((void**)&deg,    g_deg);
    cudaGetSymbolAddress((void**)&bucket, g_bucket);

    // init
    zero_i_kernel<<<(n + 255) / 256, 256>>>(deg, n);
    zero_f4_kernel<<<(GG * HH / 4 + 255) / 256, 256>>>(pool, GG * HH / 4);
    zero_f4_kernel<<<(GG / 4 + 255) / 256, 256>>>(cnt, GG / 4);

    // adjacency build (once, reused by both layers)
    fill_kernel<<<(E / 4 + 255) / 256, 256>>>(src, dst, deg, bucket, E);
    dinv_kernel<<<(n + 255) / 256, 256>>>(deg, dinv, n);

    // layer 1
    gemm_mma_kernel<FIN, false><<<(n + 127) / 128, 128>>>(x, W1, dinv, XS, n);
    gather_kernel<false><<<(n * 8 + 255) / 256, 256>>>(
        deg, bucket, XS, dinv, b1, H1, nullptr, nullptr, nullptr, n);

    // layer 2 (fused relu + mean-pool reduction)
    gemm_mma_kernel<HH, true><<<(n + 127) / 128, 128>>>(H1, W2, dinv, XS, n);
    gather_kernel<true><<<(n * 8 + 255) / 256, 256>>>(
        deg, bucket, XS, dinv, b2, nullptr, batch, pool, cnt, n);

    // head
    head_kernel<<<(GG + 255) / 256, 256>>>(pool, cnt, Wl, bl, (float*)d_out);
}

// round 5
// speedup vs baseline: 2.0063x; 1.0072x over previous
#include <cuda_runtime.h>
#include <cuda_bf16.h>
#include <cstdint>

#define NN   100000
#define FIN  128
#define HH   64
#define GG   512
#define CAP  64

// Scratch (device globals — allocation-free per harness rules)
__device__ __align__(16) float g_dinv[NN];
__device__ __align__(16) __nv_bfloat16 g_xs[NN * HH];  // scaled x@W (bf16)
__device__ __align__(16) __nv_bfloat16 g_h1[NN * HH];  // h after layer 1 (bf16)
__device__ __align__(16) float g_pool[GG * HH];
__device__ __align__(16) float g_cnt[GG];
__device__            int   g_deg[NN];
__device__ __align__(16) int g_bucket[NN * CAP];

// ---------------------------------------------------------------------------
__global__ void zero_f4_kernel(float* __restrict__ p, int n4) {
    int i = blockIdx.x * blockDim.x + threadIdx.x;
    if (i < n4) ((float4*)p)[i] = make_float4(0.f, 0.f, 0.f, 0.f);
}

__global__ void zero_i_kernel(int* __restrict__ p, int n) {
    int i = blockIdx.x * blockDim.x + threadIdx.x;
    if (i < n) p[i] = 0;
}

// bucket fill, 4 edges per thread
__global__ void fill_kernel(const int* __restrict__ src, const int* __restrict__ dst,
                            int* __restrict__ cur, int* __restrict__ bucket, int E) {
    int base = (blockIdx.x * blockDim.x + threadIdx.x) * 4;
    #pragma unroll
    for (int j = 0; j < 4; j++) {
        int i = base + j;
        if (i < E) {
            int d = __ldg(&dst[i]);
            int s = __ldg(&src[i]);
            int pos = atomicAdd(&cur[d], 1);
            if (pos < CAP) bucket[d * CAP + pos] = s;
        }
    }
}

__global__ void dinv_kernel(const int* __restrict__ deg, float* __restrict__ dinv, int n) {
    int i = blockIdx.x * blockDim.x + threadIdx.x;
    if (i < n) dinv[i] = rsqrtf((float)deg[i] + 1.0f);
}

// ---------------------------------------------------------------------------
// Tensor-core GEMM: out[row,:] = bf16( dinv[row] * (X[row,:] @ W) ),  W:[K,64] fp32
// mma.sync.m16n8k8 tf32. Block: 128 threads (4 warps), tile M=128, N=64.
// BF16IN: X is bf16 (exact tf32 operand via <<16); else fp32 (rna-rounded).
#define WS_STRIDE 72
#define AS_STRIDE 20

__device__ __forceinline__ uint32_t f2tf32(float f) {
    uint32_t r;
    asm("cvt.rna.tf32.f32 %0, %1;" : "=r"(r) : "f"(f));
    return r;
}

template <int K, bool BF16IN>
__global__ __launch_bounds__(128) void gemm_mma_kernel(
        const void* __restrict__ Xv, const float* __restrict__ W,
        const float* __restrict__ dinv, __nv_bfloat16* __restrict__ out, int n) {
    __shared__ uint32_t Ws[K * WS_STRIDE];
    __shared__ uint32_t As[128 * AS_STRIDE];

    const int tid  = threadIdx.x;
    const int row0 = blockIdx.x * 128;
    const int warp = tid >> 5;
    const int lane = tid & 31;
    const int r    = lane >> 2;
    const int cq   = lane & 3;
    const int mrow = warp * 32;

    for (int i = tid; i < K * 64; i += 128) {
        int k = i >> 6, nn = i & 63;
        Ws[k * WS_STRIDE + nn] = f2tf32(W[i]);
    }

    float acc[2][8][4];
    #pragma unroll
    for (int mt = 0; mt < 2; mt++)
        #pragma unroll
        for (int nb = 0; nb < 8; nb++)
            #pragma unroll
            for (int c = 0; c < 4; c++) acc[mt][nb][c] = 0.f;

    for (int kc = 0; kc < K; kc += 16) {
        __syncthreads();
        #pragma unroll
        for (int j = 0; j < 16; j++) {
            int i   = tid + j * 128;
            int rr  = i >> 4;
            int c   = i & 15;
            int row = row0 + rr;
            uint32_t v;
            if (BF16IN) {
                const __nv_bfloat16* X = (const __nv_bfloat16*)Xv;
                uint16_t h = (row < n) ? *(const uint16_t*)&X[(long)row * K + kc + c] : 0;
                v = ((uint32_t)h) << 16;   // exact tf32
            } else {
                const float* X = (const float*)Xv;
                float f = (row < n) ? X[(long)row * K + kc + c] : 0.0f;
                v = f2tf32(f);
            }
            As[rr * AS_STRIDE + c] = v;
        }
        __syncthreads();

        #pragma unroll
        for (int ks = 0; ks < 2; ks++) {
            int kl = ks * 8;
            uint32_t a[2][4];
            #pragma unroll
            for (int mt = 0; mt < 2; mt++) {
                int rr = mrow + mt * 16;
                a[mt][0] = As[(rr + r)     * AS_STRIDE + kl + cq];
                a[mt][1] = As[(rr + r + 8) * AS_STRIDE + kl + cq];
                a[mt][2] = As[(rr + r)     * AS_STRIDE + kl + cq + 4];
                a[mt][3] = As[(rr + r + 8) * AS_STRIDE + kl + cq + 4];
            }
            #pragma unroll
            for (int nb = 0; nb < 8; nb++) {
                uint32_t b0 = Ws[(kc + kl + cq)     * WS_STRIDE + nb * 8 + r];
                uint32_t b1 = Ws[(kc + kl + cq + 4) * WS_STRIDE + nb * 8 + r];
                #pragma unroll
                for (int mt = 0; mt < 2; mt++) {
                    asm volatile(
                        "mma.sync.aligned.m16n8k8.row.col.f32.tf32.tf32.f32 "
                        "{%0,%1,%2,%3}, {%4,%5,%6,%7}, {%8,%9}, {%0,%1,%2,%3};"
                        : "+f"(acc[mt][nb][0]), "+f"(acc[mt][nb][1]),
                          "+f"(acc[mt][nb][2]), "+f"(acc[mt][nb][3])
                        : "r"(a[mt][0]), "r"(a[mt][1]), "r"(a[mt][2]), "r"(a[mt][3]),
                          "r"(b0), "r"(b1));
                }
            }
        }
    }

    // epilogue: scale by dinv, store bf16x2 pairs
    #pragma unroll
    for (int mt = 0; mt < 2; mt++) {
        int row_a = row0 + mrow + mt * 16 + r;
        int row_b = row_a + 8;
        float sa = (row_a < n) ? dinv[row_a] : 0.f;
        float sb = (row_b < n) ? dinv[row_b] : 0.f;
        #pragma unroll
        for (int nb = 0; nb < 8; nb++) {
            int col = nb * 8 + cq * 2;
            if (row_a < n) {
                __nv_bfloat162 v = __float22bfloat162_rn(
                    make_float2(acc[mt][nb][0] * sa, acc[mt][nb][1] * sa));
                *(__nv_bfloat162*)&out[(long)row_a * HH + col] = v;
            }
            if (row_b < n) {
                __nv_bfloat162 v = __float22bfloat162_rn(
                    make_float2(acc[mt][nb][2] * sb, acc[mt][nb][3] * sb));
                *(__nv_bfloat162*)&out[(long)row_b * HH + col] = v;
            }
        }
    }
}

// ---------------------------------------------------------------------------
// Gather: h[n] = relu(dinv[n] * (xs[n] + sum_{s in bucket} xs[s]) + b)
// bf16 rows (128 B). 8 threads per node, each lane owns one uint4 (8 bf16).
__device__ __forceinline__ void acc_u4(float* a, uint4 v) {
    float2 f;
    f = __bfloat1622float2(*(__nv_bfloat162*)&v.x); a[0] += f.x; a[1] += f.y;
    f = __bfloat1622float2(*(__nv_bfloat162*)&v.y); a[2] += f.x; a[3] += f.y;
    f = __bfloat1622float2(*(__nv_bfloat162*)&v.z); a[4] += f.x; a[5] += f.y;
    f = __bfloat1622float2(*(__nv_bfloat162*)&v.w); a[6] += f.x; a[7] += f.y;
}

template <bool POOL>
__global__ void gather_kernel(const int* __restrict__ deg, const int* __restrict__ bucket,
                              const __nv_bfloat16* __restrict__ xs,
                              const float* __restrict__ dinv,
                              const float* __restrict__ b,
                              __nv_bfloat16* __restrict__ out,
                              const int* __restrict__ batch,
                              float* __restrict__ pool, float* __restrict__ cntg,
                              int n) {
    int t = blockIdx.x * blockDim.x + threadIdx.x;
    int node = t >> 3;
    if (node >= n) return;
    int lane8 = t & 7;
    int c = lane8 << 3;                    // column base (8 cols)
    const uint4* xrow = (const uint4*)(xs) + node * 8 + lane8;  // HH bf16 = 8 uint4

    int dcount = __ldg(&deg[node]);
    if (dcount > CAP) dcount = CAP;
    const int* lst = bucket + node * CAP;

    float acc[8] = {};
    acc_u4(acc, __ldg((const uint4*)xs + (long)node * 8 + lane8));  // self-loop

    int e = 0;
    for (; e + 4 <= dcount; e += 4) {
        int s0 = __ldg(&lst[e + 0]);
        int s1 = __ldg(&lst[e + 1]);
        int s2 = __ldg(&lst[e + 2]);
        int s3 = __ldg(&lst[e + 3]);
        uint4 v0 = __ldg((const uint4*)xs + (long)s0 * 8 + lane8);
        uint4 v1 = __ldg((const uint4*)xs + (long)s1 * 8 + lane8);
        uint4 v2 = __ldg((const uint4*)xs + (long)s2 * 8 + lane8);
        uint4 v3 = __ldg((const uint4*)xs + (long)s3 * 8 + lane8);
        acc_u4(acc, v0); acc_u4(acc, v1); acc_u4(acc, v2); acc_u4(acc, v3);
    }
    for (; e < dcount; e++) {
        int s = __ldg(&lst[e]);
        acc_u4(acc, __ldg((const uint4*)xs + (long)s * 8 + lane8));
    }
    (void)xrow;

    float sc = __ldg(&dinv[node]);
    float o[8];
    #pragma unroll
    for (int i = 0; i < 8; i++)
        o[i] = fmaxf(fmaf(sc, acc[i], __ldg(&b[c + i])), 0.f);

    if (!POOL) {
        uint4 pk;
        __nv_bfloat162 h0 = __float22bfloat162_rn(make_float2(o[0], o[1]));
        __nv_bfloat162 h1 = __float22bfloat162_rn(make_float2(o[2], o[3]));
        __nv_bfloat162 h2 = __float22bfloat162_rn(make_float2(o[4], o[5]));
        __nv_bfloat162 h3 = __float22bfloat162_rn(make_float2(o[6], o[7]));
        pk.x = *(uint32_t*)&h0; pk.y = *(uint32_t*)&h1;
        pk.z = *(uint32_t*)&h2; pk.w = *(uint32_t*)&h3;
        *((uint4*)out + (long)node * 8 + lane8) = pk;
    } else {
        int g = __ldg(&batch[node]);
        float* p = pool + g * HH + c;
        asm volatile("red.global.add.v4.f32 [%0], {%1,%2,%3,%4};"
                     :: "l"(p), "f"(o[0]), "f"(o[1]), "f"(o[2]), "f"(o[3]) : "memory");
        asm volatile("red.global.add.v4.f32 [%0], {%1,%2,%3,%4};"
                     :: "l"(p + 4), "f"(o[4]), "f"(o[5]), "f"(o[6]), "f"(o[7]) : "memory");
        if (lane8 == 0) atomicAdd(&cntg[g], 1.0f);
    }
}

// ---------------------------------------------------------------------------
__global__ void head_kernel(const float* __restrict__ pool, const float* __restrict__ cnt,
                            const float* __restrict__ Wl, const float* __restrict__ bl,
                            float* __restrict__ out) {
    int g = blockIdx.x * blockDim.x + threadIdx.x;
    if (g >= GG) return;
    float inv = 1.0f / fmaxf(cnt[g], 1.0f);
    float acc = 0.f;
    #pragma unroll
    for (int k = 0; k < HH; k++) acc += pool[g * HH + k] * __ldg(&Wl[k]);
    float z = acc * inv + __ldg(&bl[0]);
    out[g] = 1.0f / (1.0f + expf(-z));
}

// ---------------------------------------------------------------------------
extern "C" void kernel_launch(void* const* d_in, const int* in_sizes, int n_in,
                              void* d_out, int out_size) {
    const float* x     = (const float*)d_in[0];
    const int*   ei    = (const int*)  d_in[1];
    const int*   batch = (const int*)  d_in[2];
    const float* W1    = (const float*)d_in[3];
    const float* b1    = (const float*)d_in[4];
    const float* W2    = (const float*)d_in[5];
    const float* b2    = (const float*)d_in[6];
    const float* Wl    = (const float*)d_in[7];
    const float* bl    = (const float*)d_in[8];

    const int n = in_sizes[0] / FIN;
    const int E = in_sizes[1] / 2;
    const int* src = ei;
    const int* dst = ei + E;

    float *dinv, *pool, *cnt;
    __nv_bfloat16 *XS, *H1;
    int *deg, *bucket;
    cudaGetSymbolAddress((void**)&dinv,   g_dinv);
    cudaGetSymbolAddress((void**)&XS,     g_xs);
    cudaGetSymbolAddress((void**)&H1,     g_h1);
    cudaGetSymbolAddress((void**)&pool,   g_pool);
    cudaGetSymbolAddress((void**)&cnt,    g_cnt);
    cudaGetSymbolAddress((void**)&deg,    g_deg);
    cudaGetSymbolAddress((void**)&bucket, g_bucket);

    // init
    zero_i_kernel<<<(n + 255) / 256, 256>>>(deg, n);
    zero_f4_kernel<<<(GG * HH / 4 + 255) / 256, 256>>>(pool, GG * HH / 4);
    zero_f4_kernel<<<(GG / 4 + 255) / 256, 256>>>(cnt, GG / 4);

    // adjacency build (once, reused by both layers)
    fill_kernel<<<(E / 4 + 255) / 256, 256>>>(src, dst, deg, bucket, E);
    dinv_kernel<<<(n + 255) / 256, 256>>>(deg, dinv, n);

    // layer 1
    gemm_mma_kernel<FIN, false><<<(n + 127) / 128, 128>>>(x, W1, dinv, XS, n);
    gather_kernel<false><<<(n * 8 + 255) / 256, 256>>>(
        deg, bucket, XS, dinv, b1, H1, nullptr, nullptr, nullptr, n);

    // layer 2 (fused relu + mean-pool reduction)
    gemm_mma_kernel<HH, true><<<(n + 127) / 128, 128>>>(H1, W2, dinv, XS, n);
    gather_kernel<true><<<(n * 8 + 255) / 256, 256>>>(
        deg, bucket, XS, dinv, b2, nullptr, batch, pool, cnt, n);

    // head
    head_kernel<<<(GG + 255) / 256, 256>>>(pool, cnt, Wl, bl, (float*)d_out);
}